// round 2
// baseline (speedup 1.0000x reference)
#include <cuda_runtime.h>
#include <cstdint>
#include <cstddef>

// ---------------------------------------------------------------------------
// GCN_21569325760838: 2-layer GCN, CSR-gather formulation.
//   hs1 = dinv[row] * (x @ W1)            (scaled in GEMM epilogue)
//   a1  = relu(dinv[d]*(sum_{s in N(d)} hs1[s] + hs1[d]) + b1)
//   hs2 = dinv[row] * (a1 @ W2)
//   out = dinv[d]*(sum hs2[s] + hs2[d]) + b2
// deg[v] = indeg(v) + 1 ; dinv = rsqrt(deg)
// ---------------------------------------------------------------------------

#define NMAX 100000
#define EMAX 1600000
#define NF1  128
#define NF2  64

__device__ int   g_is64;
__device__ int   g_deg [NMAX];          // in-degree (without self loop)
__device__ int   g_off [NMAX + 1];
__device__ int   g_cur [NMAX];
__device__ int   g_csr [EMAX];          // src indices grouped by dst
__device__ float g_dinv[NMAX];
__device__ float g_h1  [(size_t)NMAX * NF1];   // dinv-scaled x@W1
__device__ float g_a1  [(size_t)NMAX * NF1];   // relu layer-1 output
__device__ float g_h2  [(size_t)NMAX * NF2];   // dinv-scaled a1@W2

// ---------------------------------------------------------------------------
__global__ void k_set_flag() { g_is64 = 1; }

// Deterministic dtype probe: reinterpret first nscan entries as int64.
__global__ void k_detect(const long long* __restrict__ p, int nscan, int n_nodes) {
    int i = blockIdx.x * blockDim.x + threadIdx.x;
    if (i < nscan) {
        long long v = p[i];
        if (v < 0 || v >= (long long)n_nodes) g_is64 = 0;
    }
}

__device__ __forceinline__ void load_edge(const void* eidx, int e, int E, int& s, int& d) {
    if (g_is64) {
        const long long* p = (const long long*)eidx;
        s = (int)p[e]; d = (int)p[(size_t)E + e];
    } else {
        const int* p = (const int*)eidx;
        s = p[e]; d = p[(size_t)E + e];
    }
}

// ---------------------------------------------------------------------------
__global__ void k_deg_init(int n) {
    int i = blockIdx.x * blockDim.x + threadIdx.x;
    if (i < n) g_deg[i] = 0;
}

__global__ void k_deg(const void* __restrict__ eidx, int E) {
    int e = blockIdx.x * blockDim.x + threadIdx.x;
    if (e >= E) return;
    int s, d;
    load_edge(eidx, e, E, s, d);
    atomicAdd(&g_deg[d], 1);
}

// Single-block scan: off[] exclusive prefix of deg, cur[]=off[], dinv=rsqrt(deg+1).
__global__ void k_scan(int n, int E) {
    __shared__ int sm[1024];
    const int t = threadIdx.x;
    const int chunk = (n + 1023) / 1024;
    const int i0 = t * chunk;
    const int i1 = min(i0 + chunk, n);
    int mysum = 0;
    for (int i = i0; i < i1; i++) mysum += g_deg[i];
    sm[t] = mysum;
    __syncthreads();
    for (int st = 1; st < 1024; st <<= 1) {
        int v = (t >= st) ? sm[t - st] : 0;
        __syncthreads();
        sm[t] += v;
        __syncthreads();
    }
    int running = sm[t] - mysum;       // exclusive prefix of my chunk
    for (int i = i0; i < i1; i++) {
        int d = g_deg[i];
        g_off[i] = running;
        g_cur[i] = running;
        g_dinv[i] = rsqrtf((float)(d + 1));
        running += d;
    }
    if (t == 0) g_off[n] = E;
}

__global__ void k_scatter(const void* __restrict__ eidx, int E) {
    int e = blockIdx.x * blockDim.x + threadIdx.x;
    if (e >= E) return;
    int s, d;
    load_edge(eidx, e, E, s, d);
    int pos = atomicAdd(&g_cur[d], 1);
    g_csr[pos] = s;
}

// ---------------------------------------------------------------------------
// fp32 tiled GEMM, row-major: C[M,N] = rowscale[m] * (A[M,K] @ B[K,N]).  N == BN.
template<int BM, int BN, int BK, int TM, int TN>
__global__ void gemm_rrr(const float* __restrict__ A, const float* __restrict__ B,
                         float* __restrict__ C, const float* __restrict__ rowscale,
                         int M, int K) {
    __shared__ float As[BM][BK + 4];
    __shared__ float Bs[BK][BN];
    constexpr int NT = (BM / TM) * (BN / TN);
    const int tx = threadIdx.x % (BN / TN);
    const int ty = threadIdx.x / (BN / TN);
    const int row0 = blockIdx.x * BM;

    float acc[TM][TN];
    #pragma unroll
    for (int i = 0; i < TM; i++)
        #pragma unroll
        for (int j = 0; j < TN; j++) acc[i][j] = 0.f;

    for (int k0 = 0; k0 < K; k0 += BK) {
        #pragma unroll
        for (int i = threadIdx.x; i < BM * BK / 4; i += NT) {
            int r = i / (BK / 4), c4 = i % (BK / 4);
            float4 v = make_float4(0.f, 0.f, 0.f, 0.f);
            if (row0 + r < M)
                v = ((const float4*)(A + (size_t)(row0 + r) * K + k0))[c4];
            *((float4*)&As[r][c4 * 4]) = v;
        }
        #pragma unroll
        for (int i = threadIdx.x; i < BK * BN / 4; i += NT) {
            int r = i / (BN / 4), c4 = i % (BN / 4);
            *((float4*)&Bs[r][c4 * 4]) =
                ((const float4*)(B + (size_t)(k0 + r) * BN))[c4];
        }
        __syncthreads();
        #pragma unroll
        for (int k = 0; k < BK; k++) {
            float a[TM], b[TN];
            #pragma unroll
            for (int i = 0; i < TM; i++) a[i] = As[ty * TM + i][k];
            #pragma unroll
            for (int j = 0; j < TN; j++) b[j] = Bs[k][tx * TN + j];
            #pragma unroll
            for (int i = 0; i < TM; i++)
                #pragma unroll
                for (int j = 0; j < TN; j++) acc[i][j] += a[i] * b[j];
        }
        __syncthreads();
    }
    #pragma unroll
    for (int i = 0; i < TM; i++) {
        int r = row0 + ty * TM + i;
        if (r < M) {
            float sc = rowscale[r];
            #pragma unroll
            for (int j = 0; j < TN; j += 4) {
                float4 v = make_float4(acc[i][j] * sc, acc[i][j+1] * sc,
                                       acc[i][j+2] * sc, acc[i][j+3] * sc);
                ((float4*)(C + (size_t)r * BN))[(tx * TN + j) / 4] = v;
            }
        }
    }
}

// ---------------------------------------------------------------------------
// Layer-1 aggregation: warp per dst node, float4 per lane (128 feats).
// a1[d] = relu(dinv[d]*(sum_{s} hs1[s] + hs1[d]) + b1)
__global__ void k_agg1(const float* __restrict__ b1, int n) {
    int node = blockIdx.x * (blockDim.x >> 5) + (threadIdx.x >> 5);
    if (node >= n) return;
    int lane = threadIdx.x & 31;

    const float4* h = (const float4*)g_h1;
    float4 acc = h[(size_t)node * 32 + lane];       // self term (already dinv-scaled)
    int j = g_off[node], jend = g_off[node + 1];
    for (; j + 1 < jend; j += 2) {
        int s0 = g_csr[j], s1 = g_csr[j + 1];
        float4 v0 = h[(size_t)s0 * 32 + lane];
        float4 v1 = h[(size_t)s1 * 32 + lane];
        acc.x += v0.x + v1.x; acc.y += v0.y + v1.y;
        acc.z += v0.z + v1.z; acc.w += v0.w + v1.w;
    }
    if (j < jend) {
        int s0 = g_csr[j];
        float4 v0 = h[(size_t)s0 * 32 + lane];
        acc.x += v0.x; acc.y += v0.y; acc.z += v0.z; acc.w += v0.w;
    }
    float w = g_dinv[node];
    float4 b = ((const float4*)b1)[lane];
    float4 o;
    o.x = fmaxf(acc.x * w + b.x, 0.f);
    o.y = fmaxf(acc.y * w + b.y, 0.f);
    o.z = fmaxf(acc.z * w + b.z, 0.f);
    o.w = fmaxf(acc.w * w + b.w, 0.f);
    ((float4*)g_a1)[(size_t)node * 32 + lane] = o;
}

// Layer-2 aggregation: warp per dst node, float2 per lane (64 feats). Writes d_out.
__global__ void k_agg2(const float* __restrict__ b2, float* __restrict__ out, int n) {
    int node = blockIdx.x * (blockDim.x >> 5) + (threadIdx.x >> 5);
    if (node >= n) return;
    int lane = threadIdx.x & 31;

    const float2* h = (const float2*)g_h2;
    float2 acc = h[(size_t)node * 32 + lane];       // self term
    int j = g_off[node], jend = g_off[node + 1];
    for (; j + 1 < jend; j += 2) {
        int s0 = g_csr[j], s1 = g_csr[j + 1];
        float2 v0 = h[(size_t)s0 * 32 + lane];
        float2 v1 = h[(size_t)s1 * 32 + lane];
        acc.x += v0.x + v1.x; acc.y += v0.y + v1.y;
    }
    if (j < jend) {
        int s0 = g_csr[j];
        float2 v0 = h[(size_t)s0 * 32 + lane];
        acc.x += v0.x; acc.y += v0.y;
    }
    float w = g_dinv[node];
    float2 b = ((const float2*)b2)[lane];
    float2 o;
    o.x = acc.x * w + b.x;
    o.y = acc.y * w + b.y;
    ((float2*)out)[(size_t)node * 32 + lane] = o;
}

// ---------------------------------------------------------------------------
extern "C" void kernel_launch(void* const* d_in, const int* in_sizes, int n_in,
                              void* d_out, int out_size) {
    const void*  eidx = d_in[0];
    const float* x    = (const float*)d_in[1];
    const float* W1   = (const float*)d_in[2];
    const float* b1   = (const float*)d_in[3];
    const float* W2   = (const float*)d_in[4];
    const float* b2   = (const float*)d_in[5];
    float* out = (float*)d_out;

    const int E = in_sizes[0] / 2;
    const int N = in_sizes[1] / NF1;

    float *p_h1, *p_a1, *p_h2, *p_dinv;
    cudaGetSymbolAddress((void**)&p_h1,   g_h1);
    cudaGetSymbolAddress((void**)&p_a1,   g_a1);
    cudaGetSymbolAddress((void**)&p_h2,   g_h2);
    cudaGetSymbolAddress((void**)&p_dinv, g_dinv);

    // dtype probe
    k_set_flag<<<1, 1>>>();
    int nscan = E < 2048 ? E : 2048;
    k_detect<<<(nscan + 255) / 256, 256>>>((const long long*)eidx, nscan, N);

    // CSR build
    k_deg_init<<<(N + 255) / 256, 256>>>(N);
    k_deg<<<(E + 255) / 256, 256>>>(eidx, E);
    k_scan<<<1, 1024>>>(N, E);
    k_scatter<<<(E + 255) / 256, 256>>>(eidx, E);

    // layer 1
    gemm_rrr<64, 128, 32, 4, 8><<<(N + 63) / 64, 256>>>(x, W1, p_h1, p_dinv, N, NF1);
    k_agg1<<<(N + 7) / 8, 256>>>(b1, N);

    // layer 2
    gemm_rrr<64, 64, 32, 4, 4><<<(N + 63) / 64, 256>>>(p_a1, W2, p_h2, p_dinv, N, NF1);
    k_agg2<<<(N + 7) / 8, 256>>>(b2, out, N);
}

// round 3
// speedup vs baseline: 1.2348x; 1.2348x over previous
#include <cuda_runtime.h>
#include <cstdint>
#include <cstddef>

// ---------------------------------------------------------------------------
// GCN_21569325760838: 2-layer GCN, CSR-gather + tf32 tensor-core GEMMs.
//   hs1 = dinv[row] * (x @ W1)            (scaled in GEMM epilogue)
//   a1  = relu(dinv[d]*(sum_{s in N(d)} hs1[s] + hs1[d]) + b1)
//   hs2 = dinv[row] * (a1 @ W2)
//   out = dinv[d]*(sum hs2[s] + hs2[d]) + b2
// ---------------------------------------------------------------------------

#define NMAX 100000
#define EMAX 1600000
#define NF1  128
#define NF2  64

__device__ int   g_is64;
__device__ int   g_deg [NMAX];          // in-degree (without self loop)
__device__ int   g_off [NMAX + 1];
__device__ int   g_cur [NMAX];
__device__ int   g_csr [EMAX];          // src indices grouped by dst
__device__ float g_dinv[NMAX];
__device__ float g_h1  [(size_t)NMAX * NF1];   // dinv-scaled x@W1
__device__ float g_a1  [(size_t)NMAX * NF1];   // relu layer-1 output
__device__ float g_h2  [(size_t)NMAX * NF2];   // dinv-scaled a1@W2

// ---------------------------------------------------------------------------
__global__ void k_set_flag() { g_is64 = 1; }

__global__ void k_detect(const long long* __restrict__ p, int nscan, int n_nodes) {
    int i = blockIdx.x * blockDim.x + threadIdx.x;
    if (i < nscan) {
        long long v = p[i];
        if (v < 0 || v >= (long long)n_nodes) g_is64 = 0;
    }
}

__device__ __forceinline__ void load_edge(const void* eidx, int e, int E, int& s, int& d) {
    if (g_is64) {
        const long long* p = (const long long*)eidx;
        s = (int)p[e]; d = (int)p[(size_t)E + e];
    } else {
        const int* p = (const int*)eidx;
        s = p[e]; d = p[(size_t)E + e];
    }
}

// ---------------------------------------------------------------------------
__global__ void k_deg_init(int n) {
    int i = blockIdx.x * blockDim.x + threadIdx.x;
    if (i < n) g_deg[i] = 0;
}

__global__ void k_deg(const void* __restrict__ eidx, int E) {
    int e = blockIdx.x * blockDim.x + threadIdx.x;
    if (e >= E) return;
    int s, d;
    load_edge(eidx, e, E, s, d);
    atomicAdd(&g_deg[d], 1);
}

// Single-block scan: off[] exclusive prefix of deg, cur[]=off[], dinv=rsqrt(deg+1).
__global__ void k_scan(int n, int E) {
    __shared__ int sm[1024];
    const int t = threadIdx.x;
    const int chunk = (n + 1023) / 1024;
    const int i0 = t * chunk;
    const int i1 = min(i0 + chunk, n);
    int mysum = 0;
    for (int i = i0; i < i1; i++) mysum += g_deg[i];
    sm[t] = mysum;
    __syncthreads();
    for (int st = 1; st < 1024; st <<= 1) {
        int v = (t >= st) ? sm[t - st] : 0;
        __syncthreads();
        sm[t] += v;
        __syncthreads();
    }
    int running = sm[t] - mysum;       // exclusive prefix of my chunk
    for (int i = i0; i < i1; i++) {
        int d = g_deg[i];
        g_off[i] = running;
        g_cur[i] = running;
        g_dinv[i] = rsqrtf((float)(d + 1));
        running += d;
    }
    if (t == 0) g_off[n] = E;
}

__global__ void k_scatter(const void* __restrict__ eidx, int E) {
    int e = blockIdx.x * blockDim.x + threadIdx.x;
    if (e >= E) return;
    int s, d;
    load_edge(eidx, e, E, s, d);
    int pos = atomicAdd(&g_cur[d], 1);
    g_csr[pos] = s;
}

// ---------------------------------------------------------------------------
// tf32 mma.sync GEMM: C[M,BN] = rowscale[m] * (A[M,K] @ B[K,BN]), row-major.
// Block: BM x BN, 8 warps, warp tile 64x32 built from m16n8k8 mmas.
// ---------------------------------------------------------------------------
__device__ __forceinline__ uint32_t f2tf32(float x) {
    uint32_t u;
    asm("cvt.rna.tf32.f32 %0, %1;" : "=r"(u) : "f"(x));
    return u;
}

template<int BM, int BN>
__global__ void __launch_bounds__(256, 1)
gemm_tf32(const float* __restrict__ A, const float* __restrict__ B,
          float* __restrict__ C, const float* __restrict__ rowscale,
          int M, int K) {
    constexpr int KC   = 32;            // k-chunk
    constexpr int AST  = KC + 4;        // A smem stride (36)
    constexpr int BST  = BN + 8;        // B smem stride (conflict-free frag loads)
    constexpr int WNUM = BN / 32;       // warps along n
    __shared__ uint32_t As[BM][AST];
    __shared__ uint32_t Bs[KC][BST];

    const int tid  = threadIdx.x;
    const int lane = tid & 31;
    const int warp = tid >> 5;
    const int gid  = lane >> 2;         // 0..7
    const int tig  = lane & 3;          // 0..3
    const int wm   = (warp / WNUM) * 64;
    const int wn   = (warp % WNUM) * 32;
    const int row0 = blockIdx.x * BM;

    float acc[4][4][4];
    #pragma unroll
    for (int mt = 0; mt < 4; mt++)
        #pragma unroll
        for (int nt = 0; nt < 4; nt++)
            #pragma unroll
            for (int i = 0; i < 4; i++) acc[mt][nt][i] = 0.f;

    for (int k0 = 0; k0 < K; k0 += KC) {
        // A tile: BM x KC
        #pragma unroll
        for (int idx = tid; idx < BM * (KC / 4); idx += 256) {
            int r = idx / (KC / 4), c4 = (idx % (KC / 4)) * 4;
            float4 v = make_float4(0.f, 0.f, 0.f, 0.f);
            if (row0 + r < M)
                v = *(const float4*)(A + (size_t)(row0 + r) * K + k0 + c4);
            As[r][c4 + 0] = f2tf32(v.x);
            As[r][c4 + 1] = f2tf32(v.y);
            As[r][c4 + 2] = f2tf32(v.z);
            As[r][c4 + 3] = f2tf32(v.w);
        }
        // B tile: KC x BN
        #pragma unroll
        for (int idx = tid; idx < KC * (BN / 4); idx += 256) {
            int r = idx / (BN / 4), c4 = (idx % (BN / 4)) * 4;
            float4 v = *(const float4*)(B + (size_t)(k0 + r) * BN + c4);
            Bs[r][c4 + 0] = f2tf32(v.x);
            Bs[r][c4 + 1] = f2tf32(v.y);
            Bs[r][c4 + 2] = f2tf32(v.z);
            Bs[r][c4 + 3] = f2tf32(v.w);
        }
        __syncthreads();

        #pragma unroll
        for (int ks = 0; ks < KC / 8; ks++) {
            const int kk = ks * 8;
            uint32_t af[4][4];
            #pragma unroll
            for (int mt = 0; mt < 4; mt++) {
                int rb = wm + mt * 16 + gid;
                af[mt][0] = As[rb    ][kk + tig];
                af[mt][1] = As[rb + 8][kk + tig];
                af[mt][2] = As[rb    ][kk + tig + 4];
                af[mt][3] = As[rb + 8][kk + tig + 4];
            }
            uint32_t bf[4][2];
            #pragma unroll
            for (int nt = 0; nt < 4; nt++) {
                int cb = wn + nt * 8 + gid;
                bf[nt][0] = Bs[kk + tig    ][cb];
                bf[nt][1] = Bs[kk + tig + 4][cb];
            }
            #pragma unroll
            for (int mt = 0; mt < 4; mt++)
                #pragma unroll
                for (int nt = 0; nt < 4; nt++) {
                    asm volatile(
                        "mma.sync.aligned.m16n8k8.row.col.f32.tf32.tf32.f32 "
                        "{%0,%1,%2,%3}, {%4,%5,%6,%7}, {%8,%9}, {%0,%1,%2,%3};\n"
                        : "+f"(acc[mt][nt][0]), "+f"(acc[mt][nt][1]),
                          "+f"(acc[mt][nt][2]), "+f"(acc[mt][nt][3])
                        : "r"(af[mt][0]), "r"(af[mt][1]),
                          "r"(af[mt][2]), "r"(af[mt][3]),
                          "r"(bf[nt][0]), "r"(bf[nt][1]));
                }
        }
        __syncthreads();
    }

    // epilogue: scale by dinv[row], store float2 pairs
    #pragma unroll
    for (int mt = 0; mt < 4; mt++) {
        int r0 = row0 + wm + mt * 16 + gid;
        int r1 = r0 + 8;
        #pragma unroll
        for (int nt = 0; nt < 4; nt++) {
            int col = wn + nt * 8 + 2 * tig;
            if (r0 < M) {
                float sc = rowscale[r0];
                *(float2*)(C + (size_t)r0 * BN + col) =
                    make_float2(acc[mt][nt][0] * sc, acc[mt][nt][1] * sc);
            }
            if (r1 < M) {
                float sc = rowscale[r1];
                *(float2*)(C + (size_t)r1 * BN + col) =
                    make_float2(acc[mt][nt][2] * sc, acc[mt][nt][3] * sc);
            }
        }
    }
}

// ---------------------------------------------------------------------------
// Layer-1 aggregation: warp per dst node, float4 per lane (128 feats).
__global__ void k_agg1(const float* __restrict__ b1, int n) {
    int node = blockIdx.x * (blockDim.x >> 5) + (threadIdx.x >> 5);
    if (node >= n) return;
    int lane = threadIdx.x & 31;

    const float4* h = (const float4*)g_h1;
    float4 acc = h[(size_t)node * 32 + lane];       // self term (already dinv-scaled)
    int j = g_off[node], jend = g_off[node + 1];
    for (; j + 1 < jend; j += 2) {
        int s0 = g_csr[j], s1 = g_csr[j + 1];
        float4 v0 = h[(size_t)s0 * 32 + lane];
        float4 v1 = h[(size_t)s1 * 32 + lane];
        acc.x += v0.x + v1.x; acc.y += v0.y + v1.y;
        acc.z += v0.z + v1.z; acc.w += v0.w + v1.w;
    }
    if (j < jend) {
        int s0 = g_csr[j];
        float4 v0 = h[(size_t)s0 * 32 + lane];
        acc.x += v0.x; acc.y += v0.y; acc.z += v0.z; acc.w += v0.w;
    }
    float w = g_dinv[node];
    float4 b = ((const float4*)b1)[lane];
    float4 o;
    o.x = fmaxf(acc.x * w + b.x, 0.f);
    o.y = fmaxf(acc.y * w + b.y, 0.f);
    o.z = fmaxf(acc.z * w + b.z, 0.f);
    o.w = fmaxf(acc.w * w + b.w, 0.f);
    ((float4*)g_a1)[(size_t)node * 32 + lane] = o;
}

// Layer-2 aggregation: warp per dst node, float2 per lane (64 feats). Writes d_out.
__global__ void k_agg2(const float* __restrict__ b2, float* __restrict__ out, int n) {
    int node = blockIdx.x * (blockDim.x >> 5) + (threadIdx.x >> 5);
    if (node >= n) return;
    int lane = threadIdx.x & 31;

    const float2* h = (const float2*)g_h2;
    float2 acc = h[(size_t)node * 32 + lane];       // self term
    int j = g_off[node], jend = g_off[node + 1];
    for (; j + 1 < jend; j += 2) {
        int s0 = g_csr[j], s1 = g_csr[j + 1];
        float2 v0 = h[(size_t)s0 * 32 + lane];
        float2 v1 = h[(size_t)s1 * 32 + lane];
        acc.x += v0.x + v1.x; acc.y += v0.y + v1.y;
    }
    if (j < jend) {
        int s0 = g_csr[j];
        float2 v0 = h[(size_t)s0 * 32 + lane];
        acc.x += v0.x; acc.y += v0.y;
    }
    float w = g_dinv[node];
    float2 b = ((const float2*)b2)[lane];
    float2 o;
    o.x = acc.x * w + b.x;
    o.y = acc.y * w + b.y;
    ((float2*)out)[(size_t)node * 32 + lane] = o;
}

// ---------------------------------------------------------------------------
extern "C" void kernel_launch(void* const* d_in, const int* in_sizes, int n_in,
                              void* d_out, int out_size) {
    const void*  eidx = d_in[0];
    const float* x    = (const float*)d_in[1];
    const float* W1   = (const float*)d_in[2];
    const float* b1   = (const float*)d_in[3];
    const float* W2   = (const float*)d_in[4];
    const float* b2   = (const float*)d_in[5];
    float* out = (float*)d_out;

    const int E = in_sizes[0] / 2;
    const int N = in_sizes[1] / NF1;

    float *p_h1, *p_a1, *p_h2, *p_dinv;
    cudaGetSymbolAddress((void**)&p_h1,   g_h1);
    cudaGetSymbolAddress((void**)&p_a1,   g_a1);
    cudaGetSymbolAddress((void**)&p_h2,   g_h2);
    cudaGetSymbolAddress((void**)&p_dinv, g_dinv);

    // dtype probe
    k_set_flag<<<1, 1>>>();
    int nscan = E < 2048 ? E : 2048;
    k_detect<<<(nscan + 255) / 256, 256>>>((const long long*)eidx, nscan, N);

    // CSR build
    k_deg_init<<<(N + 255) / 256, 256>>>(N);
    k_deg<<<(E + 255) / 256, 256>>>(eidx, E);
    k_scan<<<1, 1024>>>(N, E);
    k_scatter<<<(E + 255) / 256, 256>>>(eidx, E);

    // layer 1:  h1 = dinv * (x @ W1)  [tf32 tensor cores]
    gemm_tf32<128, 128><<<(N + 127) / 128, 256>>>(x, W1, p_h1, p_dinv, N, NF1);
    k_agg1<<<(N + 7) / 8, 256>>>(b1, N);

    // layer 2:  h2 = dinv * (a1 @ W2)
    gemm_tf32<256, 64><<<(N + 255) / 256, 256>>>(p_a1, W2, p_h2, p_dinv, N, NF1);
    k_agg2<<<(N + 7) / 8, 256>>>(b2, out, N);
}

// round 4
// speedup vs baseline: 1.2968x; 1.0502x over previous
#include <cuda_runtime.h>
#include <cuda_fp16.h>
#include <cstdint>
#include <cstddef>

// ---------------------------------------------------------------------------
// GCN_21569325760838: 2-layer GCN, CSR-gather, tf32/fp16 tensor-core GEMMs,
// fp16 intermediate storage (fp32 accumulation everywhere).
//   hs1 = dinv[row] * (x @ W1)                      (tf32 mma, fp16 out)
//   a1  = relu(dinv[d]*(sum_{s in N(d)} hs1[s] + hs1[d]) + b1)   (fp16 out)
//   hs2 = dinv[row] * (a1 @ W2)                     (fp16 mma, fp16 out)
//   out = dinv[d]*(sum hs2[s] + hs2[d]) + b2        (fp32 out)
// ---------------------------------------------------------------------------

#define NMAX 100000
#define EMAX 1600000
#define NF1  128
#define NF2  64

__device__ int    g_is64;
__device__ int    g_deg [NMAX];
__device__ int    g_off [NMAX + 1];
__device__ int    g_cur [NMAX];
__device__ int    g_csr [EMAX];
__device__ float  g_dinv[NMAX];
__device__ __half g_h1  [(size_t)NMAX * NF1];
__device__ __half g_a1  [(size_t)NMAX * NF1];
__device__ __half g_h2  [(size_t)NMAX * NF2];
__device__ __half g_w2t [NF2 * NF1];          // W2 transposed [N][K], fp16

// ---------------------------------------------------------------------------
__global__ void k_set_flag() { g_is64 = 1; }

__global__ void k_detect(const long long* __restrict__ p, int nscan, int n_nodes) {
    int i = blockIdx.x * blockDim.x + threadIdx.x;
    if (i < nscan) {
        long long v = p[i];
        if (v < 0 || v >= (long long)n_nodes) g_is64 = 0;
    }
}

__device__ __forceinline__ void load_edge(const void* eidx, int e, int E, int& s, int& d) {
    if (g_is64) {
        const long long* p = (const long long*)eidx;
        s = (int)p[e]; d = (int)p[(size_t)E + e];
    } else {
        const int* p = (const int*)eidx;
        s = p[e]; d = p[(size_t)E + e];
    }
}

// ---------------------------------------------------------------------------
__global__ void k_deg_init(int n) {
    int i = blockIdx.x * blockDim.x + threadIdx.x;
    if (i < n) g_deg[i] = 0;
}

__global__ void k_deg(const void* __restrict__ eidx, int E) {
    int e = blockIdx.x * blockDim.x + threadIdx.x;
    if (e >= E) return;
    int s, d;
    load_edge(eidx, e, E, s, d);
    atomicAdd(&g_deg[d], 1);
}

__global__ void k_scan(int n, int E) {
    __shared__ int sm[1024];
    const int t = threadIdx.x;
    const int chunk = (n + 1023) / 1024;
    const int i0 = t * chunk;
    const int i1 = min(i0 + chunk, n);
    int mysum = 0;
    for (int i = i0; i < i1; i++) mysum += g_deg[i];
    sm[t] = mysum;
    __syncthreads();
    for (int st = 1; st < 1024; st <<= 1) {
        int v = (t >= st) ? sm[t - st] : 0;
        __syncthreads();
        sm[t] += v;
        __syncthreads();
    }
    int running = sm[t] - mysum;
    for (int i = i0; i < i1; i++) {
        int d = g_deg[i];
        g_off[i] = running;
        g_cur[i] = running;
        g_dinv[i] = rsqrtf((float)(d + 1));
        running += d;
    }
    if (t == 0) g_off[n] = E;
}

__global__ void k_scatter(const void* __restrict__ eidx, int E) {
    int e = blockIdx.x * blockDim.x + threadIdx.x;
    if (e >= E) return;
    int s, d;
    load_edge(eidx, e, E, s, d);
    int pos = atomicAdd(&g_cur[d], 1);
    g_csr[pos] = s;
}

// W2 fp32 [K][N] -> W2t fp16 [N][K]
__global__ void k_w2t(const float* __restrict__ W2) {
    int i = blockIdx.x * blockDim.x + threadIdx.x;   // i = n*NF1 + k
    if (i >= NF2 * NF1) return;
    int n = i / NF1, k = i % NF1;
    g_w2t[i] = __float2half(W2[(size_t)k * NF2 + n]);
}

// ---------------------------------------------------------------------------
// GEMM1: tf32 mma, C fp16 = rowscale[m] * (A[M,128] @ B[128,128])
// Block 128x128, 8 warps, warp tile 64x32 of m16n8k8.
// ---------------------------------------------------------------------------
__device__ __forceinline__ uint32_t f2tf32(float x) {
    uint32_t u;
    asm("cvt.rna.tf32.f32 %0, %1;" : "=r"(u) : "f"(x));
    return u;
}

__global__ void __launch_bounds__(256, 1)
gemm1_tf32(const float* __restrict__ A, const float* __restrict__ B,
           __half* __restrict__ C, const float* __restrict__ rowscale, int M) {
    constexpr int BM = 128, BN = 128, KC = 32;
    constexpr int AST = KC + 4, BST = BN + 8;
    constexpr int K = NF1, WNUM = BN / 32;
    __shared__ uint32_t As[BM][AST];
    __shared__ uint32_t Bs[KC][BST];

    const int tid  = threadIdx.x;
    const int lane = tid & 31;
    const int warp = tid >> 5;
    const int gid  = lane >> 2;
    const int tig  = lane & 3;
    const int wm   = (warp / WNUM) * 64;
    const int wn   = (warp % WNUM) * 32;
    const int row0 = blockIdx.x * BM;

    float acc[4][4][4];
    #pragma unroll
    for (int mt = 0; mt < 4; mt++)
        #pragma unroll
        for (int nt = 0; nt < 4; nt++)
            #pragma unroll
            for (int i = 0; i < 4; i++) acc[mt][nt][i] = 0.f;

    for (int k0 = 0; k0 < K; k0 += KC) {
        #pragma unroll
        for (int idx = tid; idx < BM * (KC / 4); idx += 256) {
            int r = idx / (KC / 4), c4 = (idx % (KC / 4)) * 4;
            float4 v = make_float4(0.f, 0.f, 0.f, 0.f);
            if (row0 + r < M)
                v = *(const float4*)(A + (size_t)(row0 + r) * K + k0 + c4);
            As[r][c4 + 0] = f2tf32(v.x);
            As[r][c4 + 1] = f2tf32(v.y);
            As[r][c4 + 2] = f2tf32(v.z);
            As[r][c4 + 3] = f2tf32(v.w);
        }
        #pragma unroll
        for (int idx = tid; idx < KC * (BN / 4); idx += 256) {
            int r = idx / (BN / 4), c4 = (idx % (BN / 4)) * 4;
            float4 v = *(const float4*)(B + (size_t)(k0 + r) * BN + c4);
            Bs[r][c4 + 0] = f2tf32(v.x);
            Bs[r][c4 + 1] = f2tf32(v.y);
            Bs[r][c4 + 2] = f2tf32(v.z);
            Bs[r][c4 + 3] = f2tf32(v.w);
        }
        __syncthreads();

        #pragma unroll
        for (int ks = 0; ks < KC / 8; ks++) {
            const int kk = ks * 8;
            uint32_t af[4][4];
            #pragma unroll
            for (int mt = 0; mt < 4; mt++) {
                int rb = wm + mt * 16 + gid;
                af[mt][0] = As[rb    ][kk + tig];
                af[mt][1] = As[rb + 8][kk + tig];
                af[mt][2] = As[rb    ][kk + tig + 4];
                af[mt][3] = As[rb + 8][kk + tig + 4];
            }
            uint32_t bf[4][2];
            #pragma unroll
            for (int nt = 0; nt < 4; nt++) {
                int cb = wn + nt * 8 + gid;
                bf[nt][0] = Bs[kk + tig    ][cb];
                bf[nt][1] = Bs[kk + tig + 4][cb];
            }
            #pragma unroll
            for (int mt = 0; mt < 4; mt++)
                #pragma unroll
                for (int nt = 0; nt < 4; nt++) {
                    asm volatile(
                        "mma.sync.aligned.m16n8k8.row.col.f32.tf32.tf32.f32 "
                        "{%0,%1,%2,%3}, {%4,%5,%6,%7}, {%8,%9}, {%0,%1,%2,%3};\n"
                        : "+f"(acc[mt][nt][0]), "+f"(acc[mt][nt][1]),
                          "+f"(acc[mt][nt][2]), "+f"(acc[mt][nt][3])
                        : "r"(af[mt][0]), "r"(af[mt][1]),
                          "r"(af[mt][2]), "r"(af[mt][3]),
                          "r"(bf[nt][0]), "r"(bf[nt][1]));
                }
        }
        __syncthreads();
    }

    #pragma unroll
    for (int mt = 0; mt < 4; mt++) {
        int r0 = row0 + wm + mt * 16 + gid;
        int r1 = r0 + 8;
        #pragma unroll
        for (int nt = 0; nt < 4; nt++) {
            int col = wn + nt * 8 + 2 * tig;
            if (r0 < M) {
                float sc = rowscale[r0];
                *(__half2*)(C + (size_t)r0 * BN + col) =
                    __floats2half2_rn(acc[mt][nt][0] * sc, acc[mt][nt][1] * sc);
            }
            if (r1 < M) {
                float sc = rowscale[r1];
                *(__half2*)(C + (size_t)r1 * BN + col) =
                    __floats2half2_rn(acc[mt][nt][2] * sc, acc[mt][nt][3] * sc);
            }
        }
    }
}

// ---------------------------------------------------------------------------
// GEMM2: fp16 mma m16n8k16, C fp16 = rowscale[m] * (A[M,128] @ W2t^T)
// A fp16 row-major [M][128]; B = g_w2t fp16 [64][128] (n-major rows).
// Block 256x64, 8 warps (4x2), warp tile 64x32.
// ---------------------------------------------------------------------------
__global__ void __launch_bounds__(256, 1)
gemm2_fp16(const __half* __restrict__ A, __half* __restrict__ C,
           const float* __restrict__ rowscale, int M) {
    constexpr int BM = 256, BN = 64, KC = 32;
    constexpr int K = NF1;
    constexpr int AST = KC + 8;    // halves (stride 40 -> 20 words, conflict-free)
    constexpr int BST = KC + 8;
    constexpr int WNUM = BN / 32;  // 2
    __shared__ __half As[BM][AST];
    __shared__ __half Bs[BN][BST];

    const int tid  = threadIdx.x;
    const int lane = tid & 31;
    const int warp = tid >> 5;
    const int gid  = lane >> 2;
    const int tig  = lane & 3;
    const int wm   = (warp / WNUM) * 64;
    const int wn   = (warp % WNUM) * 32;
    const int row0 = blockIdx.x * BM;

    float acc[4][4][4];
    #pragma unroll
    for (int mt = 0; mt < 4; mt++)
        #pragma unroll
        for (int nt = 0; nt < 4; nt++)
            #pragma unroll
            for (int i = 0; i < 4; i++) acc[mt][nt][i] = 0.f;

    for (int k0 = 0; k0 < K; k0 += KC) {
        // A tile: BM x KC halves, uint2 (4 halves) per load
        #pragma unroll
        for (int idx = tid; idx < BM * (KC / 4); idx += 256) {
            int r = idx / (KC / 4), c4 = (idx % (KC / 4)) * 4;
            uint2 v = make_uint2(0u, 0u);
            if (row0 + r < M)
                v = *(const uint2*)(A + (size_t)(row0 + r) * K + k0 + c4);
            *(uint2*)&As[r][c4] = v;
        }
        // B tile: BN x KC halves from g_w2t
        #pragma unroll
        for (int idx = tid; idx < BN * (KC / 4); idx += 256) {
            int n = idx / (KC / 4), c4 = (idx % (KC / 4)) * 4;
            *(uint2*)&Bs[n][c4] = *(const uint2*)(g_w2t + (size_t)n * K + k0 + c4);
        }
        __syncthreads();

        #pragma unroll
        for (int ks = 0; ks < KC / 16; ks++) {
            const int kk = ks * 16;
            uint32_t af[4][4];
            #pragma unroll
            for (int mt = 0; mt < 4; mt++) {
                int rb = wm + mt * 16 + gid;
                af[mt][0] = *(const uint32_t*)&As[rb    ][kk + 2 * tig];
                af[mt][1] = *(const uint32_t*)&As[rb + 8][kk + 2 * tig];
                af[mt][2] = *(const uint32_t*)&As[rb    ][kk + 2 * tig + 8];
                af[mt][3] = *(const uint32_t*)&As[rb + 8][kk + 2 * tig + 8];
            }
            uint32_t bf[4][2];
            #pragma unroll
            for (int nt = 0; nt < 4; nt++) {
                int cb = wn + nt * 8 + gid;
                bf[nt][0] = *(const uint32_t*)&Bs[cb][kk + 2 * tig];
                bf[nt][1] = *(const uint32_t*)&Bs[cb][kk + 2 * tig + 8];
            }
            #pragma unroll
            for (int mt = 0; mt < 4; mt++)
                #pragma unroll
                for (int nt = 0; nt < 4; nt++) {
                    asm volatile(
                        "mma.sync.aligned.m16n8k16.row.col.f32.f16.f16.f32 "
                        "{%0,%1,%2,%3}, {%4,%5,%6,%7}, {%8,%9}, {%0,%1,%2,%3};\n"
                        : "+f"(acc[mt][nt][0]), "+f"(acc[mt][nt][1]),
                          "+f"(acc[mt][nt][2]), "+f"(acc[mt][nt][3])
                        : "r"(af[mt][0]), "r"(af[mt][1]),
                          "r"(af[mt][2]), "r"(af[mt][3]),
                          "r"(bf[nt][0]), "r"(bf[nt][1]));
                }
        }
        __syncthreads();
    }

    #pragma unroll
    for (int mt = 0; mt < 4; mt++) {
        int r0 = row0 + wm + mt * 16 + gid;
        int r1 = r0 + 8;
        #pragma unroll
        for (int nt = 0; nt < 4; nt++) {
            int col = wn + nt * 8 + 2 * tig;
            if (r0 < M) {
                float sc = rowscale[r0];
                *(__half2*)(C + (size_t)r0 * BN + col) =
                    __floats2half2_rn(acc[mt][nt][0] * sc, acc[mt][nt][1] * sc);
            }
            if (r1 < M) {
                float sc = rowscale[r1];
                *(__half2*)(C + (size_t)r1 * BN + col) =
                    __floats2half2_rn(acc[mt][nt][2] * sc, acc[mt][nt][3] * sc);
            }
        }
    }
}

// ---------------------------------------------------------------------------
// Layer-1 aggregation: warp per dst node; lane covers 4 feats (uint2 = 4 halves).
__global__ void k_agg1(const float* __restrict__ b1, int n) {
    int node = blockIdx.x * (blockDim.x >> 5) + (threadIdx.x >> 5);
    if (node >= n) return;
    int lane = threadIdx.x & 31;

    const uint2* h = (const uint2*)g_h1;
    uint2 sv = h[(size_t)node * 32 + lane];
    float2 lo = __half22float2(*(__half2*)&sv.x);
    float2 hi = __half22float2(*(__half2*)&sv.y);
    float4 acc = make_float4(lo.x, lo.y, hi.x, hi.y);

    int j = g_off[node], jend = g_off[node + 1];
    for (; j + 1 < jend; j += 2) {
        int s0 = g_csr[j], s1 = g_csr[j + 1];
        uint2 v0 = h[(size_t)s0 * 32 + lane];
        uint2 v1 = h[(size_t)s1 * 32 + lane];
        float2 a0 = __half22float2(*(__half2*)&v0.x);
        float2 a1 = __half22float2(*(__half2*)&v0.y);
        float2 c0 = __half22float2(*(__half2*)&v1.x);
        float2 c1 = __half22float2(*(__half2*)&v1.y);
        acc.x += a0.x + c0.x; acc.y += a0.y + c0.y;
        acc.z += a1.x + c1.x; acc.w += a1.y + c1.y;
    }
    if (j < jend) {
        uint2 v0 = h[(size_t)g_csr[j] * 32 + lane];
        float2 a0 = __half22float2(*(__half2*)&v0.x);
        float2 a1 = __half22float2(*(__half2*)&v0.y);
        acc.x += a0.x; acc.y += a0.y; acc.z += a1.x; acc.w += a1.y;
    }
    float w = g_dinv[node];
    float4 b = ((const float4*)b1)[lane];
    float ox = fmaxf(acc.x * w + b.x, 0.f);
    float oy = fmaxf(acc.y * w + b.y, 0.f);
    float oz = fmaxf(acc.z * w + b.z, 0.f);
    float ow = fmaxf(acc.w * w + b.w, 0.f);
    uint2 o;
    *(__half2*)&o.x = __floats2half2_rn(ox, oy);
    *(__half2*)&o.y = __floats2half2_rn(oz, ow);
    ((uint2*)g_a1)[(size_t)node * 32 + lane] = o;
}

// Layer-2 aggregation: warp per dst node; lane covers 2 feats (half2). fp32 out.
__global__ void k_agg2(const float* __restrict__ b2, float* __restrict__ out, int n) {
    int node = blockIdx.x * (blockDim.x >> 5) + (threadIdx.x >> 5);
    if (node >= n) return;
    int lane = threadIdx.x & 31;

    const __half2* h = (const __half2*)g_h2;
    float2 acc = __half22float2(h[(size_t)node * 32 + lane]);
    int j = g_off[node], jend = g_off[node + 1];
    for (; j + 1 < jend; j += 2) {
        int s0 = g_csr[j], s1 = g_csr[j + 1];
        float2 v0 = __half22float2(h[(size_t)s0 * 32 + lane]);
        float2 v1 = __half22float2(h[(size_t)s1 * 32 + lane]);
        acc.x += v0.x + v1.x; acc.y += v0.y + v1.y;
    }
    if (j < jend) {
        float2 v0 = __half22float2(h[(size_t)g_csr[j] * 32 + lane]);
        acc.x += v0.x; acc.y += v0.y;
    }
    float w = g_dinv[node];
    float2 b = ((const float2*)b2)[lane];
    ((float2*)out)[(size_t)node * 32 + lane] =
        make_float2(acc.x * w + b.x, acc.y * w + b.y);
}

// ---------------------------------------------------------------------------
extern "C" void kernel_launch(void* const* d_in, const int* in_sizes, int n_in,
                              void* d_out, int out_size) {
    const void*  eidx = d_in[0];
    const float* x    = (const float*)d_in[1];
    const float* W1   = (const float*)d_in[2];
    const float* b1   = (const float*)d_in[3];
    const float* W2   = (const float*)d_in[4];
    const float* b2   = (const float*)d_in[5];
    float* out = (float*)d_out;

    const int E = in_sizes[0] / 2;
    const int N = in_sizes[1] / NF1;

    __half *p_h1, *p_a1, *p_h2;
    float  *p_dinv;
    cudaGetSymbolAddress((void**)&p_h1,   g_h1);
    cudaGetSymbolAddress((void**)&p_a1,   g_a1);
    cudaGetSymbolAddress((void**)&p_h2,   g_h2);
    cudaGetSymbolAddress((void**)&p_dinv, g_dinv);

    // dtype probe
    k_set_flag<<<1, 1>>>();
    int nscan = E < 2048 ? E : 2048;
    k_detect<<<(nscan + 255) / 256, 256>>>((const long long*)eidx, nscan, N);

    // CSR build + weight conversion
    k_deg_init<<<(N + 255) / 256, 256>>>(N);
    k_deg<<<(E + 255) / 256, 256>>>(eidx, E);
    k_w2t<<<(NF1 * NF2 + 255) / 256, 256>>>(W2);
    k_scan<<<1, 1024>>>(N, E);
    k_scatter<<<(E + 255) / 256, 256>>>(eidx, E);

    // layer 1
    gemm1_tf32<<<(N + 127) / 128, 256>>>(x, W1, p_h1, p_dinv, N);
    k_agg1<<<(N + 7) / 8, 256>>>(b1, N);

    // layer 2
    gemm2_fp16<<<(N + 255) / 256, 256>>>(p_a1, p_h2, p_dinv, N);
    k_agg2<<<(N + 7) / 8, 256>>>(b2, out, N);
}